// round 13
// baseline (speedup 1.0000x reference)
#include <cuda_runtime.h>
#include <cuda_bf16.h>
#include <cstdint>

#define Bb 4
#define Nn 4096
#define Cc 64
#define Hh 4
#define DH 16
#define KNNk 10
#define KSk 4
#define Mm 256
#define ROWS_TOT (Bb * Nn)

// ---------------- scratch (device globals; no allocation allowed) ----------------
__device__ float g_qkv[ROWS_TOT * 192];   // [row][q(64) k(64) v(64)]
__device__ float g_x[ROWS_TOT * 64];      // residual after attention
__device__ int   g_nbr[ROWS_TOT * KNNk];  // per-batch-local neighbor indices
__device__ unsigned char g_mask[ROWS_TOT];
__device__ float4 g_bpts[Bb * Nn];        // binned unmasked points (x,y,z,idx-bits)
__device__ int2   g_cellrange[Bb * 4096]; // per-cell (start, count) into g_bpts
__device__ int    g_qord[Bb * Nn];        // all queries sorted by cell (locality)

// ---------------- k0: normalize mask dtype (u8 / i32 / f32) into g_mask ----------
__global__ void k0_mask(const void* mp) {
    __shared__ int mode;
    const unsigned char* u = (const unsigned char*)mp;
    if (threadIdx.x == 0) {
        bool anyHigh = false, anyOff = false;
        for (int i = 0; i < 256; ++i) {
            unsigned char b = u[i];
            if (b > 1) anyHigh = true;
            if ((i & 3) != 0 && b != 0) anyOff = true;
        }
        mode = anyHigh ? 2 : (anyOff ? 0 : 1);
    }
    __syncthreads();
    int i = blockIdx.x * blockDim.x + threadIdx.x;
    unsigned char v;
    if (mode == 0)      v = (u[i] != 0);
    else if (mode == 1) v = (((const int*)mp)[i] != 0);
    else                v = (((const float*)mp)[i] != 0.0f);
    g_mask[i] = v;
}

// ---------------- k1: LN1 + QKV GEMM (32 rows / block) ----------------
__global__ void k1_ln_qkv(const float* __restrict__ x,
                          const float* __restrict__ g1, const float* __restrict__ b1,
                          const float* __restrict__ wq, const float* __restrict__ bq) {
    extern __shared__ float sm1[];
    float* ws  = sm1;            // 12288 = 64*192
    float* bs  = ws + 12288;     // 192
    float* xsT = bs + 192;       // 64 * 36 (transposed x-hat, pitch 36)
    int tid = threadIdx.x;
    int rowBase = blockIdx.x * 32;

    for (int i = tid; i < 12288; i += 256) ws[i] = wq[i];
    if (tid < 192) bs[tid] = bq[tid];

    int w = tid >> 5, lane = tid & 31;
#pragma unroll
    for (int rr = 0; rr < 4; ++rr) {
        int r = w * 4 + rr;
        const float* xr = x + (size_t)(rowBase + r) * 64;
        float a0 = xr[lane], a1 = xr[lane + 32];
        float s = a0 + a1, ss = a0 * a0 + a1 * a1;
#pragma unroll
        for (int o = 16; o; o >>= 1) {
            s  += __shfl_xor_sync(0xffffffffu, s, o);
            ss += __shfl_xor_sync(0xffffffffu, ss, o);
        }
        float m   = s * (1.f / 64.f);
        float var = fmaxf(ss * (1.f / 64.f) - m * m, 0.f);
        float inv = rsqrtf(var + 1e-5f);
        xsT[lane * 36 + r]        = (a0 - m) * inv * __ldg(&g1[lane])      + __ldg(&b1[lane]);
        xsT[(lane + 32) * 36 + r] = (a1 - m) * inv * __ldg(&g1[lane + 32]) + __ldg(&b1[lane + 32]);
    }
    __syncthreads();

    if (tid < 192) {
        int c = tid;
#pragma unroll
        for (int g = 0; g < 4; ++g) {
            float bb = bs[c];
            float acc[8];
#pragma unroll
            for (int i = 0; i < 8; ++i) acc[i] = bb;
#pragma unroll 4
            for (int k = 0; k < 64; ++k) {
                float wv  = ws[k * 192 + c];
                float4 xa = *(const float4*)&xsT[k * 36 + g * 8];
                float4 xb = *(const float4*)&xsT[k * 36 + g * 8 + 4];
                acc[0] = fmaf(xa.x, wv, acc[0]);
                acc[1] = fmaf(xa.y, wv, acc[1]);
                acc[2] = fmaf(xa.z, wv, acc[2]);
                acc[3] = fmaf(xa.w, wv, acc[3]);
                acc[4] = fmaf(xb.x, wv, acc[4]);
                acc[5] = fmaf(xb.y, wv, acc[5]);
                acc[6] = fmaf(xb.z, wv, acc[6]);
                acc[7] = fmaf(xb.w, wv, acc[7]);
            }
#pragma unroll
            for (int i = 0; i < 8; ++i)
                g_qkv[(size_t)(rowBase + g * 8 + i) * 192 + c] = acc[i];
        }
    }
}

// ---------------- k2a: bin points into 16^3 grid (counting sort) -----------------
// pass 0: unmasked points -> g_bpts + g_cellrange.  pass 1: all points -> g_qord.
__global__ void k2a_bins(const float* __restrict__ coords) {
    __shared__ unsigned int cnts[4096];
    __shared__ unsigned int starts[4096];
    __shared__ unsigned int wsum[32];
    int b = blockIdx.x, tid = threadIdx.x;           // 1024 threads
    const float* cb = coords + (size_t)b * Nn * 3;
    int lane = tid & 31, wid = tid >> 5;

    for (int pass = 0; pass < 2; ++pass) {
        for (int i = tid; i < 4096; i += 1024) cnts[i] = 0;
        __syncthreads();
        for (int i = tid; i < Nn; i += 1024) {
            if (pass == 0 && !g_mask[b * Nn + i]) continue;
            float x = cb[i * 3], y = cb[i * 3 + 1], z = cb[i * 3 + 2];
            int cx = min(15, (int)x), cy = min(15, (int)y), cz = min(15, (int)z);
            atomicAdd(&cnts[(cz * 16 + cy) * 16 + cx], 1u);
        }
        __syncthreads();
        // exclusive scan of 4096 counts (4 per thread)
        unsigned v0 = cnts[tid * 4], v1 = cnts[tid * 4 + 1],
                 v2 = cnts[tid * 4 + 2], v3 = cnts[tid * 4 + 3];
        unsigned tot = v0 + v1 + v2 + v3;
        unsigned inc = tot;
#pragma unroll
        for (int o = 1; o < 32; o <<= 1) {
            unsigned n = __shfl_up_sync(0xffffffffu, inc, o);
            if (lane >= o) inc += n;
        }
        if (lane == 31) wsum[wid] = inc;
        __syncthreads();
        if (wid == 0) {
            unsigned t = wsum[lane];
            unsigned i2 = t;
#pragma unroll
            for (int o = 1; o < 32; o <<= 1) {
                unsigned n = __shfl_up_sync(0xffffffffu, i2, o);
                if (lane >= o) i2 += n;
            }
            wsum[lane] = i2 - t;
        }
        __syncthreads();
        unsigned base = wsum[wid] + (inc - tot);
        unsigned s0 = base, s1 = base + v0, s2 = s1 + v1, s3 = s2 + v2;
        starts[tid * 4] = s0; starts[tid * 4 + 1] = s1;
        starts[tid * 4 + 2] = s2; starts[tid * 4 + 3] = s3;
        if (pass == 0) {
            g_cellrange[b * 4096 + tid * 4 + 0] = make_int2((int)s0, (int)v0);
            g_cellrange[b * 4096 + tid * 4 + 1] = make_int2((int)s1, (int)v1);
            g_cellrange[b * 4096 + tid * 4 + 2] = make_int2((int)s2, (int)v2);
            g_cellrange[b * 4096 + tid * 4 + 3] = make_int2((int)s3, (int)v3);
        }
        __syncthreads();
        for (int i = tid; i < Nn; i += 1024) {
            if (pass == 0 && !g_mask[b * Nn + i]) continue;
            float x = cb[i * 3], y = cb[i * 3 + 1], z = cb[i * 3 + 2];
            int cx = min(15, (int)x), cy = min(15, (int)y), cz = min(15, (int)z);
            unsigned pos = atomicAdd(&starts[(cz * 16 + cy) * 16 + cx], 1u);
            if (pass == 0) g_bpts[b * Nn + pos] = make_float4(x, y, z, __int_as_float(i));
            else           g_qord[b * Nn + pos] = i;
        }
        __syncthreads();
    }
}

// ---------------- k2b: exact KNN, warp-per-query, packed-u64 register top-10 -----
// key = (bits(d_true) << 32) | idx, d_true = max(|c|^2 - 2 q.c + |q|^2, 0) >= 0,
// so unsigned key order == lexicographic (distance, index): lowest index wins ties,
// matching jax.lax.top_k. ALL list accesses statically indexed (no local memory).
// INFKEY encodes (+inf, idx 0) so a degenerate (<10 points) batch yields idx 0.
#define INFKEY 0x7F80000000000000ull

__global__ void k2b_knn(const float* __restrict__ coords) {
    int lane = threadIdx.x & 31, warp = threadIdx.x >> 5;
    int b = blockIdx.y;
    int t = blockIdx.x * 8 + warp;                   // bin-ordered query slot
    int q = g_qord[b * Nn + t];
    const float* cb = coords + (size_t)b * Nn * 3;
    float qx = cb[q * 3], qy = cb[q * 3 + 1], qz = cb[q * 3 + 2];
    float qq = fmaf(qx, qx, fmaf(qy, qy, qz * qz));
    float nx = -2.f * qx, ny = -2.f * qy, nz = -2.f * qz;
    int qcx = min(15, (int)qx), qcy = min(15, (int)qy), qcz = min(15, (int)qz);

    const float4* bp = &g_bpts[b * Nn];
    const int2*   cr = &g_cellrange[b * 4096];

    unsigned long long key[KNNk];
#pragma unroll
    for (int i = 0; i < KNNk; ++i) key[i] = INFKEY;

    // static-index sorted insert (register-resident compare/select chain)
    auto insertKey = [&](unsigned long long kk) {
#pragma unroll
        for (int k = 0; k < KNNk; ++k) {
            bool pr = kk < key[k];
            unsigned long long tv = key[k];
            key[k] = pr ? kk : tv;
            kk     = pr ? tv : kk;
        }
    };

    // phase 1: full 5x5x5 neighborhood (shells 0..2), cells distributed over lanes
#pragma unroll
    for (int it = 0; it < 4; ++it) {
        int c5 = lane + it * 32;
        if (c5 < 125) {
            int dz = c5 / 25 - 2;
            int rem = c5 - (c5 / 25) * 25;
            int dy = rem / 5 - 2, dx = rem - (rem / 5) * 5 - 2;
            int z = qcz + dz, y = qcy + dy, xx = qcx + dx;
            if ((unsigned)xx <= 15u && (unsigned)y <= 15u && (unsigned)z <= 15u) {
                int2 rg = __ldg(&cr[(z * 16 + y) * 16 + xx]);
                int pe = rg.x + rg.y;
                for (int p = rg.x; p < pe; ++p) {
                    float4 c = __ldg(&bp[p]);
                    float cc = fmaf(c.x, c.x, fmaf(c.y, c.y, c.z * c.z));
                    float dd = fmaf(nx, c.x, fmaf(ny, c.y, fmaf(nz, c.z, cc)));
                    float dt = fmaxf(dd + qq, 0.f);
                    unsigned long long kk =
                        ((unsigned long long)__float_as_uint(dt) << 32) |
                        (unsigned int)__float_as_int(c.w);
                    if (kk < key[KNNk - 1]) insertKey(kk);
                }
            }
        }
    }

    // destructive merge: 10 rounds of warp-min over heads; lane r keeps rank r.
    unsigned long long gkey = INFKEY;
    auto merge10 = [&]() {
#pragma unroll
        for (int r = 0; r < KNNk; ++r) {
            unsigned long long m = key[0];
#pragma unroll
            for (int o = 16; o; o >>= 1) {
                unsigned long long om = __shfl_xor_sync(0xffffffffu, m, o);
                m = (om < m) ? om : m;
            }
            if (lane == r) gkey = m;
            if (key[0] == m) {
#pragma unroll
                for (int k = 0; k < KNNk - 1; ++k) key[k] = key[k + 1];
                key[KNNk - 1] = INFKEY;
            }
        }
    };
    merge10();
    float d9 = __uint_as_float((unsigned)(__shfl_sync(0xffffffffu, gkey, 9) >> 32));

    // phase 2: rare outer shells (corner queries with sparse 5x5x5).
    // Ring-s cells hold points >= (s-1) away; stop when (s-1)^2 > d9 (true dist^2).
    for (int s = 3; s < 16; ++s) {
        if ((float)((s - 1) * (s - 1)) > d9) break;          // warp-uniform
        int w1 = 2 * s + 1, ncell = w1 * w1 * w1;
        bool added = false;
        for (int c5 = lane; c5 < ncell; c5 += 32) {
            int dz = c5 / (w1 * w1) - s, dy = (c5 / w1) % w1 - s, dx = c5 % w1 - s;
            int m = max(abs(dx), max(abs(dy), abs(dz)));
            if (m != s) continue;                            // ring only
            int z = qcz + dz, y = qcy + dy, xx = qcx + dx;
            if ((unsigned)xx > 15u || (unsigned)y > 15u || (unsigned)z > 15u) continue;
            int2 rg = __ldg(&cr[(z * 16 + y) * 16 + xx]);
            int pe = rg.x + rg.y;
            for (int p = rg.x; p < pe; ++p) {
                float4 c = __ldg(&bp[p]);
                float cc = fmaf(c.x, c.x, fmaf(c.y, c.y, c.z * c.z));
                float dd = fmaf(nx, c.x, fmaf(ny, c.y, fmaf(nz, c.z, cc)));
                float dt = fmaxf(dd + qq, 0.f);
                unsigned long long kk =
                    ((unsigned long long)__float_as_uint(dt) << 32) |
                    (unsigned int)__float_as_int(c.w);
                if (kk < key[KNNk - 1]) { insertKey(kk); added = true; }
            }
        }
        if (__any_sync(0xffffffffu, added)) {
            insertKey(gkey);     // put extracted global entries back in play
            gkey = INFKEY;
            merge10();
            d9 = __uint_as_float((unsigned)(__shfl_sync(0xffffffffu, gkey, 9) >> 32));
        }
    }

    if (lane < KNNk)
        g_nbr[(size_t)(b * Nn + q) * KNNk + lane] = (int)(unsigned)(gkey & 0xffffffffu);
}

// ---------------- k3: attention (64 rows / block, warp loops 8 rows) -------------
__global__ void k3_attn(const float* __restrict__ inputs,
                        const float* __restrict__ wproj, const float* __restrict__ bproj) {
    __shared__ float wp[4096];
    __shared__ float bp[64];
    __shared__ __align__(16) float qs[8][64];
    __shared__ float sc[8][40];
    __shared__ float swt[8][16];
    __shared__ int   sjg[8][16];
    __shared__ int   snb[8][KNNk];
    __shared__ float ovec[8][64];

    int tid = threadIdx.x, w = tid >> 5, lane = tid & 31;
    for (int i = tid; i < 4096; i += 256) wp[i] = wproj[i];
    if (tid < 64) bp[tid] = bproj[tid];
    __syncthreads();

    for (int r8 = 0; r8 < 8; ++r8) {
        int row  = blockIdx.x * 64 + w * 8 + r8;
        int base = row & ~(Nn - 1);

        const float* qr = &g_qkv[(size_t)row * 192];
        qs[w][lane]      = qr[lane];
        qs[w][lane + 32] = qr[lane + 32];
        if (lane < KNNk) snb[w][lane] = g_nbr[(size_t)row * KNNk + lane];
        __syncwarp();

        for (int t = lane; t < Hh * KNNk; t += 32) {
            int h = t / KNNk, j = t - h * KNNk;
            int jl = snb[w][j];
            const float* kp = &g_qkv[(size_t)(base + jl) * 192 + 64 + h * DH];
            const float* qp = &qs[w][h * DH];
            float4 k0 = *(const float4*)(kp);
            float4 k1 = *(const float4*)(kp + 4);
            float4 k2 = *(const float4*)(kp + 8);
            float4 k3 = *(const float4*)(kp + 12);
            float4 q0 = *(const float4*)(qp);
            float4 q1 = *(const float4*)(qp + 4);
            float4 q2 = *(const float4*)(qp + 8);
            float4 q3 = *(const float4*)(qp + 12);
            float acc = k0.x * q0.x + k0.y * q0.y + k0.z * q0.z + k0.w * q0.w
                      + k1.x * q1.x + k1.y * q1.y + k1.z * q1.z + k1.w * q1.w
                      + k2.x * q2.x + k2.y * q2.y + k2.z * q2.z + k2.w * q2.w
                      + k3.x * q3.x + k3.y * q3.y + k3.z * q3.z + k3.w * q3.w;
            float s = acc * 0.25f;
            if (!g_mask[base + jl]) s -= 1e9f;
            sc[w][t] = s;
        }
        __syncwarp();

        if (lane < Hh) {
            int h = lane;
            float bv0 = -3.4e38f, bv1 = -3.4e38f, bv2 = -3.4e38f, bv3 = -3.4e38f;
            int   bi0 = 0, bi1 = 0, bi2 = 0, bi3 = 0;
#pragma unroll
            for (int j = 0; j < KNNk; ++j) {
                float v = sc[w][h * KNNk + j]; int vi = j;
                if (v > bv0) { float t0 = bv0; int ti = bi0; bv0 = v; bi0 = vi; v = t0; vi = ti; }
                if (v > bv1) { float t0 = bv1; int ti = bi1; bv1 = v; bi1 = vi; v = t0; vi = ti; }
                if (v > bv2) { float t0 = bv2; int ti = bi2; bv2 = v; bi2 = vi; v = t0; vi = ti; }
                if (v > bv3) { float t0 = bv3; int ti = bi3; bv3 = v; bi3 = vi; v = t0; vi = ti; }
            }
            float e1 = __expf(bv1 - bv0), e2 = __expf(bv2 - bv0), e3 = __expf(bv3 - bv0);
            float inv = 1.f / (1.f + e1 + e2 + e3);
            swt[w][h * 4 + 0] = inv;
            swt[w][h * 4 + 1] = e1 * inv;
            swt[w][h * 4 + 2] = e2 * inv;
            swt[w][h * 4 + 3] = e3 * inv;
            sjg[w][h * 4 + 0] = base + snb[w][bi0];
            sjg[w][h * 4 + 1] = base + snb[w][bi1];
            sjg[w][h * 4 + 2] = base + snb[w][bi2];
            sjg[w][h * 4 + 3] = base + snb[w][bi3];
        }
        __syncwarp();

        {
            int c0 = lane, c1 = lane + 32;
            int h0 = c0 >> 4, h1 = c1 >> 4;
            float a0 = 0.f, a1 = 0.f;
#pragma unroll
            for (int s = 0; s < KSk; ++s) {
                a0 += swt[w][h0 * 4 + s] * g_qkv[(size_t)sjg[w][h0 * 4 + s] * 192 + 128 + c0];
                a1 += swt[w][h1 * 4 + s] * g_qkv[(size_t)sjg[w][h1 * 4 + s] * 192 + 128 + c1];
            }
            ovec[w][c0] = a0; ovec[w][c1] = a1;
        }
        __syncwarp();

        {
            float acc0 = bp[lane], acc1 = bp[lane + 32];
#pragma unroll 4
            for (int k = 0; k < 64; ++k) {
                float ov = ovec[w][k];
                acc0 = fmaf(ov, wp[k * 64 + lane], acc0);
                acc1 = fmaf(ov, wp[k * 64 + lane + 32], acc1);
            }
            float half0 = g_mask[row] ? 0.5f : 0.f;
            const float* ir = inputs + (size_t)row * 64;
            g_x[(size_t)row * 64 + lane]      = fmaf(half0, acc0, ir[lane]);
            g_x[(size_t)row * 64 + lane + 32] = fmaf(half0, acc1, ir[lane + 32]);
        }
        __syncwarp();
    }
}

// ---------------- k4: LN2 + MLP (64 rows / block, 512 threads) -------------------
__global__ void k4_mlp(const float* __restrict__ g2, const float* __restrict__ b2,
                       const float* __restrict__ w1, const float* __restrict__ b1,
                       const float* __restrict__ w2, const float* __restrict__ b2o,
                       float* __restrict__ out) {
    extern __shared__ float sm4[];
    float* w1s = sm4;             // 16384 = 64*256
    float* w2s = w1s + 16384;     // 16384 = 256*64
    float* b1s = w2s + 16384;     // 256
    float* xsT = b1s + 256;       // 64 * 68
    float* h1T = xsT + 4352;      // 256 * 68
    int tid = threadIdx.x;        // 512 threads
    int rowBase = blockIdx.x * 64;

    for (int i = tid; i < 16384; i += 512) { w1s[i] = w1[i]; w2s[i] = w2[i]; }
    if (tid < 256) b1s[tid] = b1[tid];

    int w = tid >> 5, lane = tid & 31;   // 16 warps x 4 rows = 64 rows
#pragma unroll
    for (int rr = 0; rr < 4; ++rr) {
        int r = w * 4 + rr;
        const float* xr = &g_x[(size_t)(rowBase + r) * 64];
        float a0 = xr[lane], a1 = xr[lane + 32];
        float s = a0 + a1, ss = a0 * a0 + a1 * a1;
#pragma unroll
        for (int o = 16; o; o >>= 1) {
            s  += __shfl_xor_sync(0xffffffffu, s, o);
            ss += __shfl_xor_sync(0xffffffffu, ss, o);
        }
        float m   = s * (1.f / 64.f);
        float var = fmaxf(ss * (1.f / 64.f) - m * m, 0.f);
        float inv = rsqrtf(var + 1e-5f);
        xsT[lane * 68 + r]        = (a0 - m) * inv * __ldg(&g2[lane])      + __ldg(&b2[lane]);
        xsT[(lane + 32) * 68 + r] = (a1 - m) * inv * __ldg(&g2[lane + 32]) + __ldg(&b2[lane + 32]);
    }
    __syncthreads();

    // h1[m][r] = gelu(xhat @ w1 + b1); thread = (col m, row-half), 4 groups of 8 rows
    {
        int mcol = tid & 255, half = tid >> 8;
#pragma unroll
        for (int g = 0; g < 4; ++g) {
            int r0 = half * 32 + g * 8;
            float bb = b1s[mcol];
            float acc[8];
#pragma unroll
            for (int i = 0; i < 8; ++i) acc[i] = bb;
#pragma unroll 4
            for (int k = 0; k < 64; ++k) {
                float wv  = w1s[k * 256 + mcol];
                float4 xa = *(const float4*)&xsT[k * 68 + r0];
                float4 xb = *(const float4*)&xsT[k * 68 + r0 + 4];
                acc[0] = fmaf(xa.x, wv, acc[0]);
                acc[1] = fmaf(xa.y, wv, acc[1]);
                acc[2] = fmaf(xa.z, wv, acc[2]);
                acc[3] = fmaf(xa.w, wv, acc[3]);
                acc[4] = fmaf(xb.x, wv, acc[4]);
                acc[5] = fmaf(xb.y, wv, acc[5]);
                acc[6] = fmaf(xb.z, wv, acc[6]);
                acc[7] = fmaf(xb.w, wv, acc[7]);
            }
#pragma unroll
            for (int i = 0; i < 8; ++i) {
                float xv = acc[i];
                float u = 0.7978845608028654f * (xv + 0.044715f * xv * xv * xv);
                float th;
                asm("tanh.approx.f32 %0, %1;" : "=f"(th) : "f"(u));
                h1T[mcol * 68 + r0 + i] = 0.5f * xv * (1.f + th);
            }
        }
    }
    __syncthreads();

    // h2[r][c] = h1 @ w2 + b2; out = 0.5*h2 + x
    {
        int c = tid & 63, rg = tid >> 6;   // 8 row-groups of 8
        float bb = __ldg(&b2o[c]);
        float acc[8];
#pragma unroll
        for (int i = 0; i < 8; ++i) acc[i] = bb;
#pragma unroll 2
        for (int k = 0; k < 256; ++k) {
            float wv  = w2s[k * 64 + c];
            float4 ha = *(const float4*)&h1T[k * 68 + rg * 8];
            float4 hb = *(const float4*)&h1T[k * 68 + rg * 8 + 4];
            acc[0] = fmaf(ha.x, wv, acc[0]);
            acc[1] = fmaf(ha.y, wv, acc[1]);
            acc[2] = fmaf(ha.z, wv, acc[2]);
            acc[3] = fmaf(ha.w, wv, acc[3]);
            acc[4] = fmaf(hb.x, wv, acc[4]);
            acc[5] = fmaf(hb.y, wv, acc[5]);
            acc[6] = fmaf(hb.z, wv, acc[6]);
            acc[7] = fmaf(hb.w, wv, acc[7]);
        }
#pragma unroll
        for (int i = 0; i < 8; ++i) {
            size_t row = (size_t)rowBase + rg * 8 + i;
            out[row * 64 + c] = fmaf(0.5f, acc[i], g_x[row * 64 + c]);
        }
    }
}

// ---------------- launch ----------------
extern "C" void kernel_launch(void* const* d_in, const int* in_sizes, int n_in,
                              void* d_out, int out_size) {
    (void)in_sizes; (void)n_in; (void)out_size;
    const float* inputs = (const float*)d_in[0];
    const float* coords = (const float*)d_in[1];
    const void*  maskp  = d_in[2];
    const float* ln1g   = (const float*)d_in[3];
    const float* ln1b   = (const float*)d_in[4];
    const float* ln2g   = (const float*)d_in[5];
    const float* ln2b   = (const float*)d_in[6];
    const float* wqkv   = (const float*)d_in[7];
    const float* bqkv   = (const float*)d_in[8];
    const float* wproj  = (const float*)d_in[9];
    const float* bproj  = (const float*)d_in[10];
    const float* w1     = (const float*)d_in[11];
    const float* b1     = (const float*)d_in[12];
    const float* w2     = (const float*)d_in[13];
    const float* b2     = (const float*)d_in[14];
    float* out = (float*)d_out;

    cudaFuncSetAttribute(k1_ln_qkv, cudaFuncAttributeMaxDynamicSharedMemorySize, 59136);
    cudaFuncSetAttribute(k4_mlp,    cudaFuncAttributeMaxDynamicSharedMemorySize, 219136);

    k0_mask<<<64, 256>>>(maskp);
    k2a_bins<<<4, 1024>>>(coords);
    k1_ln_qkv<<<512, 256, 59136>>>(inputs, ln1g, ln1b, wqkv, bqkv);
    k2b_knn<<<dim3(512, 4), 256>>>(coords);
    k3_attn<<<256, 256>>>(inputs, wproj, bproj);
    k4_mlp<<<256, 512, 219136>>>(ln2g, ln2b, w1, b1, w2, b2, out);
}

// round 16
// speedup vs baseline: 1.7752x; 1.7752x over previous
#include <cuda_runtime.h>
#include <cuda_bf16.h>
#include <cstdint>

#define Bb 4
#define Nn 4096
#define Cc 64
#define Hh 4
#define DH 16
#define KNNk 10
#define KSk 4
#define Mm 256
#define ROWS_TOT (Bb * Nn)
#define INF_F __int_as_float(0x7f800000)
#define INFKEY 0x7F80000000000000ull

// ---------------- scratch (device globals; no allocation allowed) ----------------
__device__ float g_qkv[ROWS_TOT * 192];   // [row][q(64) k(64) v(64)]
__device__ float g_x[ROWS_TOT * 64];      // residual after attention
__device__ int   g_nbr[ROWS_TOT * KNNk];  // per-batch-local neighbor indices
__device__ unsigned char g_mask[ROWS_TOT];
__device__ float4 g_bpts[Bb * Nn];        // binned unmasked points (x,y,z,idx-bits)
__device__ int2   g_cellrange[Bb * 4096]; // per-cell (start, count) into g_bpts
__device__ int    g_qord[Bb * Nn];        // all queries sorted by cell (locality)

// ---------------- k0: normalize mask dtype (u8 / i32 / f32) into g_mask ----------
__global__ void k0_mask(const void* mp) {
    __shared__ int mode;
    const unsigned char* u = (const unsigned char*)mp;
    if (threadIdx.x == 0) {
        bool anyHigh = false, anyOff = false;
        for (int i = 0; i < 256; ++i) {
            unsigned char b = u[i];
            if (b > 1) anyHigh = true;
            if ((i & 3) != 0 && b != 0) anyOff = true;
        }
        mode = anyHigh ? 2 : (anyOff ? 0 : 1);
    }
    __syncthreads();
    int i = blockIdx.x * blockDim.x + threadIdx.x;
    unsigned char v;
    if (mode == 0)      v = (u[i] != 0);
    else if (mode == 1) v = (((const int*)mp)[i] != 0);
    else                v = (((const float*)mp)[i] != 0.0f);
    g_mask[i] = v;
}

// ---------------- k1: LN1 + QKV GEMM (32 rows / block) ----------------
__global__ void k1_ln_qkv(const float* __restrict__ x,
                          const float* __restrict__ g1, const float* __restrict__ b1,
                          const float* __restrict__ wq, const float* __restrict__ bq) {
    extern __shared__ float sm1[];
    float* ws  = sm1;            // 12288 = 64*192
    float* bs  = ws + 12288;     // 192
    float* xsT = bs + 192;       // 64 * 36 (transposed x-hat, pitch 36)
    int tid = threadIdx.x;
    int rowBase = blockIdx.x * 32;

    for (int i = tid; i < 12288; i += 256) ws[i] = wq[i];
    if (tid < 192) bs[tid] = bq[tid];

    int w = tid >> 5, lane = tid & 31;
#pragma unroll
    for (int rr = 0; rr < 4; ++rr) {
        int r = w * 4 + rr;
        const float* xr = x + (size_t)(rowBase + r) * 64;
        float a0 = xr[lane], a1 = xr[lane + 32];
        float s = a0 + a1, ss = a0 * a0 + a1 * a1;
#pragma unroll
        for (int o = 16; o; o >>= 1) {
            s  += __shfl_xor_sync(0xffffffffu, s, o);
            ss += __shfl_xor_sync(0xffffffffu, ss, o);
        }
        float m   = s * (1.f / 64.f);
        float var = fmaxf(ss * (1.f / 64.f) - m * m, 0.f);
        float inv = rsqrtf(var + 1e-5f);
        xsT[lane * 36 + r]        = (a0 - m) * inv * __ldg(&g1[lane])      + __ldg(&b1[lane]);
        xsT[(lane + 32) * 36 + r] = (a1 - m) * inv * __ldg(&g1[lane + 32]) + __ldg(&b1[lane + 32]);
    }
    __syncthreads();

    if (tid < 192) {
        int c = tid;
#pragma unroll
        for (int g = 0; g < 4; ++g) {
            float bb = bs[c];
            float acc[8];
#pragma unroll
            for (int i = 0; i < 8; ++i) acc[i] = bb;
#pragma unroll 4
            for (int k = 0; k < 64; ++k) {
                float wv  = ws[k * 192 + c];
                float4 xa = *(const float4*)&xsT[k * 36 + g * 8];
                float4 xb = *(const float4*)&xsT[k * 36 + g * 8 + 4];
                acc[0] = fmaf(xa.x, wv, acc[0]);
                acc[1] = fmaf(xa.y, wv, acc[1]);
                acc[2] = fmaf(xa.z, wv, acc[2]);
                acc[3] = fmaf(xa.w, wv, acc[3]);
                acc[4] = fmaf(xb.x, wv, acc[4]);
                acc[5] = fmaf(xb.y, wv, acc[5]);
                acc[6] = fmaf(xb.z, wv, acc[6]);
                acc[7] = fmaf(xb.w, wv, acc[7]);
            }
#pragma unroll
            for (int i = 0; i < 8; ++i)
                g_qkv[(size_t)(rowBase + g * 8 + i) * 192 + c] = acc[i];
        }
    }
}

// ---------------- k2a: bin points into 16^3 grid (counting sort) -----------------
__global__ void k2a_bins(const float* __restrict__ coords) {
    __shared__ unsigned int cnts[4096];
    __shared__ unsigned int starts[4096];
    __shared__ unsigned int wsum[32];
    int b = blockIdx.x, tid = threadIdx.x;           // 1024 threads
    const float* cb = coords + (size_t)b * Nn * 3;
    int lane = tid & 31, wid = tid >> 5;

    for (int pass = 0; pass < 2; ++pass) {
        for (int i = tid; i < 4096; i += 1024) cnts[i] = 0;
        __syncthreads();
        for (int i = tid; i < Nn; i += 1024) {
            if (pass == 0 && !g_mask[b * Nn + i]) continue;
            float x = cb[i * 3], y = cb[i * 3 + 1], z = cb[i * 3 + 2];
            int cx = min(15, (int)x), cy = min(15, (int)y), cz = min(15, (int)z);
            atomicAdd(&cnts[(cz * 16 + cy) * 16 + cx], 1u);
        }
        __syncthreads();
        unsigned v0 = cnts[tid * 4], v1 = cnts[tid * 4 + 1],
                 v2 = cnts[tid * 4 + 2], v3 = cnts[tid * 4 + 3];
        unsigned tot = v0 + v1 + v2 + v3;
        unsigned inc = tot;
#pragma unroll
        for (int o = 1; o < 32; o <<= 1) {
            unsigned n = __shfl_up_sync(0xffffffffu, inc, o);
            if (lane >= o) inc += n;
        }
        if (lane == 31) wsum[wid] = inc;
        __syncthreads();
        if (wid == 0) {
            unsigned t = wsum[lane];
            unsigned i2 = t;
#pragma unroll
            for (int o = 1; o < 32; o <<= 1) {
                unsigned n = __shfl_up_sync(0xffffffffu, i2, o);
                if (lane >= o) i2 += n;
            }
            wsum[lane] = i2 - t;
        }
        __syncthreads();
        unsigned base = wsum[wid] + (inc - tot);
        unsigned s0 = base, s1 = base + v0, s2 = s1 + v1, s3 = s2 + v2;
        starts[tid * 4] = s0; starts[tid * 4 + 1] = s1;
        starts[tid * 4 + 2] = s2; starts[tid * 4 + 3] = s3;
        if (pass == 0) {
            g_cellrange[b * 4096 + tid * 4 + 0] = make_int2((int)s0, (int)v0);
            g_cellrange[b * 4096 + tid * 4 + 1] = make_int2((int)s1, (int)v1);
            g_cellrange[b * 4096 + tid * 4 + 2] = make_int2((int)s2, (int)v2);
            g_cellrange[b * 4096 + tid * 4 + 3] = make_int2((int)s3, (int)v3);
        }
        __syncthreads();
        for (int i = tid; i < Nn; i += 1024) {
            if (pass == 0 && !g_mask[b * Nn + i]) continue;
            float x = cb[i * 3], y = cb[i * 3 + 1], z = cb[i * 3 + 2];
            int cx = min(15, (int)x), cy = min(15, (int)y), cz = min(15, (int)z);
            unsigned pos = atomicAdd(&starts[(cz * 16 + cy) * 16 + cx], 1u);
            if (pass == 0) g_bpts[b * Nn + pos] = make_float4(x, y, z, __int_as_float(i));
            else           g_qord[b * Nn + pos] = i;
        }
        __syncthreads();
    }
}

// ---------------- k2b: exact KNN, warp-per-query, load-balanced flat scan --------
// Fast path: 5x5x5 block = 25 contiguous point spans (x-contiguity of counting
// sort). Warp scan of span lengths -> flattened candidate list; candidate c is
// processed by lane c%32 (warp-uniform, no divergent loops). total<=128 means ALL
// candidates are stored -> exact top-10 via 10 float-min extraction rounds.
// Outer shells (d9 >= 4) and overflow (total>128) use the u64 sorted-list path.
__global__ void k2b_knn(const float* __restrict__ coords) {
    int lane = threadIdx.x & 31, warp = threadIdx.x >> 5;
    int b = blockIdx.y;
    int t = blockIdx.x * 8 + warp;                   // bin-ordered query slot
    int q = g_qord[b * Nn + t];
    const float* cb = coords + (size_t)b * Nn * 3;
    float qx = cb[q * 3], qy = cb[q * 3 + 1], qz = cb[q * 3 + 2];
    float qq = fmaf(qx, qx, fmaf(qy, qy, qz * qz));
    float nx = -2.f * qx, ny = -2.f * qy, nz = -2.f * qz;
    int qcx = min(15, (int)qx), qcy = min(15, (int)qy), qcz = min(15, (int)qz);

    const float4* bp = &g_bpts[b * Nn];
    const int2*   cr = &g_cellrange[b * 4096];

    // ---- row spans for the 5x5x5 block (lane < 25 owns one (dz,dy) row) ----
    int rowLen = 0, rowStart = 0;
    if (lane < 25) {
        int dz = lane / 5 - 2, dy = lane % 5 - 2;
        int z = qcz + dz, y = qcy + dy;
        if ((unsigned)z <= 15u && (unsigned)y <= 15u) {
            int xlo = max(qcx - 2, 0), xhi = min(qcx + 2, 15);
            int cbase = (z * 16 + y) * 16;
            int2 rlo = __ldg(&cr[cbase + xlo]);
            int2 rhi = __ldg(&cr[cbase + xhi]);
            rowStart = rlo.x;
            rowLen   = rhi.x + rhi.y - rlo.x;
        }
    }
    int pfx = rowLen;
#pragma unroll
    for (int o = 1; o < 32; o <<= 1) {
        int n = __shfl_up_sync(0xffffffffu, pfx, o);
        if (lane >= o) pfx += n;
    }
    int total = __shfl_sync(0xffffffffu, pfx, 31);
    int exq = (lane < 25) ? (pfx - rowLen) : 0x7fffffff;  // exclusive prefix

    float gd = INF_F; int gi = 0;                    // lane r holds rank-r result
    float d9;

    // u64 machinery (overflow fallback + outer shells)
    unsigned long long key[KNNk];
    unsigned long long gkey = INFKEY;
    auto insertKey = [&](unsigned long long kk) {
#pragma unroll
        for (int k = 0; k < KNNk; ++k) {
            bool pr = kk < key[k];
            unsigned long long tv = key[k];
            key[k] = pr ? kk : tv;
            kk     = pr ? tv : kk;
        }
    };
    auto merge10 = [&]() {
#pragma unroll
        for (int r = 0; r < KNNk; ++r) {
            unsigned long long m = key[0];
#pragma unroll
            for (int o = 16; o; o >>= 1) {
                unsigned long long om = __shfl_xor_sync(0xffffffffu, m, o);
                m = (om < m) ? om : m;
            }
            if (lane == r) gkey = m;
            if (key[0] == m) {
#pragma unroll
                for (int k = 0; k < KNNk - 1; ++k) key[k] = key[k + 1];
                key[KNNk - 1] = INFKEY;
            }
        }
    };

    if (total <= 128) {
        // ---- fast path: flattened, load-balanced, warp-uniform ----
        float sd[4]; int si[4];
#pragma unroll
        for (int i = 0; i < 4; ++i) { sd[i] = INF_F; si[i] = 0; }
#pragma unroll
        for (int it = 0; it < 4; ++it) {
            int c = it * 32 + lane;
            if (c < total) {
                int r = 0, v;
                v = __shfl_sync(0xffffffffu, exq, 16);     if (v <= c) r = 16;
                v = __shfl_sync(0xffffffffu, exq, r + 8);  if (v <= c) r += 8;
                v = __shfl_sync(0xffffffffu, exq, r + 4);  if (v <= c) r += 4;
                v = __shfl_sync(0xffffffffu, exq, r + 2);  if (v <= c) r += 2;
                v = __shfl_sync(0xffffffffu, exq, r + 1);  if (v <= c) r += 1;
                int ex = __shfl_sync(0xffffffffu, exq, r);
                int st = __shfl_sync(0xffffffffu, rowStart, r);
                float4 c4 = __ldg(&bp[st + (c - ex)]);
                float cc = fmaf(c4.x, c4.x, fmaf(c4.y, c4.y, c4.z * c4.z));
                float dd = fmaf(nx, c4.x, fmaf(ny, c4.y, fmaf(nz, c4.z, cc)));
                sd[it] = fmaxf(dd + qq, 0.f);
                si[it] = __float_as_int(c4.w);
            } else {
                // shfls must stay convergent: dummy participation
                __shfl_sync(0xffffffffu, exq, 16);
                __shfl_sync(0xffffffffu, exq, 0);
                __shfl_sync(0xffffffffu, exq, 0);
                __shfl_sync(0xffffffffu, exq, 0);
                __shfl_sync(0xffffffffu, exq, 0);
                __shfl_sync(0xffffffffu, exq, 0);
                __shfl_sync(0xffffffffu, rowStart, 0);
            }
        }
        // sort 4 per lane (network 0-1,2-3,0-2,1-3,1-2), static indices only
#define CSW(A,B) { bool sw = sd[A] > sd[B]; float td = sd[A]; int ti = si[A]; \
                   sd[A] = sw ? sd[B] : sd[A]; si[A] = sw ? si[B] : si[A];     \
                   sd[B] = sw ? td : sd[B];    si[B] = sw ? ti : si[B]; }
        CSW(0,1) CSW(2,3) CSW(0,2) CSW(1,3) CSW(1,2)
#undef CSW
        // 10 extraction rounds on per-lane heads (float min + ballot winner)
#pragma unroll
        for (int r = 0; r < KNNk; ++r) {
            float m = sd[0];
#pragma unroll
            for (int o = 16; o; o >>= 1)
                m = fminf(m, __shfl_xor_sync(0xffffffffu, m, o));
            unsigned ball = __ballot_sync(0xffffffffu, sd[0] == m);
            int src = __ffs(ball) - 1;
            int wi = __shfl_sync(0xffffffffu, si[0], src);
            if (lane == r) { gd = m; gi = wi; }
            if (lane == src) {
                sd[0] = sd[1]; si[0] = si[1];
                sd[1] = sd[2]; si[1] = si[2];
                sd[2] = sd[3]; si[2] = si[3];
                sd[3] = INF_F; si[3] = 0;
            }
        }
        d9 = __shfl_sync(0xffffffffu, gd, 9);
    } else {
        // ---- overflow fallback (astronomically rare): u64 cells-per-lane ----
#pragma unroll
        for (int i = 0; i < KNNk; ++i) key[i] = INFKEY;
#pragma unroll
        for (int it = 0; it < 4; ++it) {
            int c5 = lane + it * 32;
            if (c5 < 125) {
                int dz = c5 / 25 - 2;
                int rem = c5 - (c5 / 25) * 25;
                int dy = rem / 5 - 2, dx = rem - (rem / 5) * 5 - 2;
                int z = qcz + dz, y = qcy + dy, xx = qcx + dx;
                if ((unsigned)xx <= 15u && (unsigned)y <= 15u && (unsigned)z <= 15u) {
                    int2 rg = __ldg(&cr[(z * 16 + y) * 16 + xx]);
                    int pe = rg.x + rg.y;
                    for (int p = rg.x; p < pe; ++p) {
                        float4 c = __ldg(&bp[p]);
                        float cc = fmaf(c.x, c.x, fmaf(c.y, c.y, c.z * c.z));
                        float dd = fmaf(nx, c.x, fmaf(ny, c.y, fmaf(nz, c.z, cc)));
                        float dt = fmaxf(dd + qq, 0.f);
                        unsigned long long kk =
                            ((unsigned long long)__float_as_uint(dt) << 32) |
                            (unsigned int)__float_as_int(c.w);
                        if (kk < key[KNNk - 1]) insertKey(kk);
                    }
                }
            }
        }
        gkey = INFKEY;
        merge10();
        gd = __uint_as_float((unsigned)(gkey >> 32));
        gi = (int)(unsigned)(gkey & 0xffffffffu);
        d9 = __shfl_sync(0xffffffffu, gd, 9);
    }

    // ---- outer shells s>=3 (runs only when d9 >= 4; u64 seeded path) ----
    if (d9 >= 4.0f) {
#pragma unroll
        for (int i = 0; i < KNNk; ++i) key[i] = INFKEY;
        gkey = ((unsigned long long)__float_as_uint(gd) << 32) | (unsigned int)gi;
        for (int s = 3; s < 16; ++s) {
            if ((float)((s - 1) * (s - 1)) > d9) break;      // warp-uniform
            int w1 = 2 * s + 1, ncell = w1 * w1 * w1;
            bool added = false;
            for (int c5 = lane; c5 < ncell; c5 += 32) {
                int dz = c5 / (w1 * w1) - s, dy = (c5 / w1) % w1 - s, dx = c5 % w1 - s;
                int m = max(abs(dx), max(abs(dy), abs(dz)));
                if (m != s) continue;                        // ring only
                int z = qcz + dz, y = qcy + dy, xx = qcx + dx;
                if ((unsigned)xx > 15u || (unsigned)y > 15u || (unsigned)z > 15u) continue;
                int2 rg = __ldg(&cr[(z * 16 + y) * 16 + xx]);
                int pe = rg.x + rg.y;
                for (int p = rg.x; p < pe; ++p) {
                    float4 c = __ldg(&bp[p]);
                    float cc = fmaf(c.x, c.x, fmaf(c.y, c.y, c.z * c.z));
                    float dd = fmaf(nx, c.x, fmaf(ny, c.y, fmaf(nz, c.z, cc)));
                    float dt = fmaxf(dd + qq, 0.f);
                    unsigned long long kk =
                        ((unsigned long long)__float_as_uint(dt) << 32) |
                        (unsigned int)__float_as_int(c.w);
                    if (kk < key[KNNk - 1]) { insertKey(kk); added = true; }
                }
            }
            if (__any_sync(0xffffffffu, added)) {
                insertKey(gkey);     // put extracted entries back in play
                gkey = INFKEY;
                merge10();
                d9 = __uint_as_float((unsigned)(__shfl_sync(0xffffffffu, gkey, 9) >> 32));
            }
        }
        gi = (int)(unsigned)(gkey & 0xffffffffu);
    }

    if (lane < KNNk)
        g_nbr[(size_t)(b * Nn + q) * KNNk + lane] = gi;
}

// ---------------- k3: attention (64 rows / block, warp loops 8 rows) -------------
__global__ void k3_attn(const float* __restrict__ inputs,
                        const float* __restrict__ wproj, const float* __restrict__ bproj) {
    __shared__ float wp[4096];
    __shared__ float bp[64];
    __shared__ __align__(16) float qs[8][64];
    __shared__ float sc[8][40];
    __shared__ float swt[8][16];
    __shared__ int   sjg[8][16];
    __shared__ int   snb[8][KNNk];
    __shared__ float ovec[8][64];

    int tid = threadIdx.x, w = tid >> 5, lane = tid & 31;
    for (int i = tid; i < 4096; i += 256) wp[i] = wproj[i];
    if (tid < 64) bp[tid] = bproj[tid];
    __syncthreads();

    for (int r8 = 0; r8 < 8; ++r8) {
        int row  = blockIdx.x * 64 + w * 8 + r8;
        int base = row & ~(Nn - 1);

        const float* qr = &g_qkv[(size_t)row * 192];
        qs[w][lane]      = qr[lane];
        qs[w][lane + 32] = qr[lane + 32];
        if (lane < KNNk) snb[w][lane] = g_nbr[(size_t)row * KNNk + lane];
        __syncwarp();

        for (int t = lane; t < Hh * KNNk; t += 32) {
            int h = t / KNNk, j = t - h * KNNk;
            int jl = snb[w][j];
            const float* kp = &g_qkv[(size_t)(base + jl) * 192 + 64 + h * DH];
            const float* qp = &qs[w][h * DH];
            float4 k0 = *(const float4*)(kp);
            float4 k1 = *(const float4*)(kp + 4);
            float4 k2 = *(const float4*)(kp + 8);
            float4 k3 = *(const float4*)(kp + 12);
            float4 q0 = *(const float4*)(qp);
            float4 q1 = *(const float4*)(qp + 4);
            float4 q2 = *(const float4*)(qp + 8);
            float4 q3 = *(const float4*)(qp + 12);
            float acc = k0.x * q0.x + k0.y * q0.y + k0.z * q0.z + k0.w * q0.w
                      + k1.x * q1.x + k1.y * q1.y + k1.z * q1.z + k1.w * q1.w
                      + k2.x * q2.x + k2.y * q2.y + k2.z * q2.z + k2.w * q2.w
                      + k3.x * q3.x + k3.y * q3.y + k3.z * q3.z + k3.w * q3.w;
            float s = acc * 0.25f;
            if (!g_mask[base + jl]) s -= 1e9f;
            sc[w][t] = s;
        }
        __syncwarp();

        if (lane < Hh) {
            int h = lane;
            float bv0 = -3.4e38f, bv1 = -3.4e38f, bv2 = -3.4e38f, bv3 = -3.4e38f;
            int   bi0 = 0, bi1 = 0, bi2 = 0, bi3 = 0;
#pragma unroll
            for (int j = 0; j < KNNk; ++j) {
                float v = sc[w][h * KNNk + j]; int vi = j;
                if (v > bv0) { float t0 = bv0; int ti = bi0; bv0 = v; bi0 = vi; v = t0; vi = ti; }
                if (v > bv1) { float t0 = bv1; int ti = bi1; bv1 = v; bi1 = vi; v = t0; vi = ti; }
                if (v > bv2) { float t0 = bv2; int ti = bi2; bv2 = v; bi2 = vi; v = t0; vi = ti; }
                if (v > bv3) { float t0 = bv3; int ti = bi3; bv3 = v; bi3 = vi; v = t0; vi = ti; }
            }
            float e1 = __expf(bv1 - bv0), e2 = __expf(bv2 - bv0), e3 = __expf(bv3 - bv0);
            float inv = 1.f / (1.f + e1 + e2 + e3);
            swt[w][h * 4 + 0] = inv;
            swt[w][h * 4 + 1] = e1 * inv;
            swt[w][h * 4 + 2] = e2 * inv;
            swt[w][h * 4 + 3] = e3 * inv;
            sjg[w][h * 4 + 0] = base + snb[w][bi0];
            sjg[w][h * 4 + 1] = base + snb[w][bi1];
            sjg[w][h * 4 + 2] = base + snb[w][bi2];
            sjg[w][h * 4 + 3] = base + snb[w][bi3];
        }
        __syncwarp();

        {
            int c0 = lane, c1 = lane + 32;
            int h0 = c0 >> 4, h1 = c1 >> 4;
            float a0 = 0.f, a1 = 0.f;
#pragma unroll
            for (int s = 0; s < KSk; ++s) {
                a0 += swt[w][h0 * 4 + s] * g_qkv[(size_t)sjg[w][h0 * 4 + s] * 192 + 128 + c0];
                a1 += swt[w][h1 * 4 + s] * g_qkv[(size_t)sjg[w][h1 * 4 + s] * 192 + 128 + c1];
            }
            ovec[w][c0] = a0; ovec[w][c1] = a1;
        }
        __syncwarp();

        {
            float acc0 = bp[lane], acc1 = bp[lane + 32];
#pragma unroll 4
            for (int k = 0; k < 64; ++k) {
                float ov = ovec[w][k];
                acc0 = fmaf(ov, wp[k * 64 + lane], acc0);
                acc1 = fmaf(ov, wp[k * 64 + lane + 32], acc1);
            }
            float half0 = g_mask[row] ? 0.5f : 0.f;
            const float* ir = inputs + (size_t)row * 64;
            g_x[(size_t)row * 64 + lane]      = fmaf(half0, acc0, ir[lane]);
            g_x[(size_t)row * 64 + lane + 32] = fmaf(half0, acc1, ir[lane + 32]);
        }
        __syncwarp();
    }
}

// ---------------- k4: LN2 + MLP (64 rows / block, 512 threads) -------------------
__global__ void k4_mlp(const float* __restrict__ g2, const float* __restrict__ b2,
                       const float* __restrict__ w1, const float* __restrict__ b1,
                       const float* __restrict__ w2, const float* __restrict__ b2o,
                       float* __restrict__ out) {
    extern __shared__ float sm4[];
    float* w1s = sm4;             // 16384 = 64*256
    float* w2s = w1s + 16384;     // 16384 = 256*64
    float* b1s = w2s + 16384;     // 256
    float* xsT = b1s + 256;       // 64 * 68
    float* h1T = xsT + 4352;      // 256 * 68
    int tid = threadIdx.x;        // 512 threads
    int rowBase = blockIdx.x * 64;

    for (int i = tid; i < 16384; i += 512) { w1s[i] = w1[i]; w2s[i] = w2[i]; }
    if (tid < 256) b1s[tid] = b1[tid];

    int w = tid >> 5, lane = tid & 31;   // 16 warps x 4 rows = 64 rows
#pragma unroll
    for (int rr = 0; rr < 4; ++rr) {
        int r = w * 4 + rr;
        const float* xr = &g_x[(size_t)(rowBase + r) * 64];
        float a0 = xr[lane], a1 = xr[lane + 32];
        float s = a0 + a1, ss = a0 * a0 + a1 * a1;
#pragma unroll
        for (int o = 16; o; o >>= 1) {
            s  += __shfl_xor_sync(0xffffffffu, s, o);
            ss += __shfl_xor_sync(0xffffffffu, ss, o);
        }
        float m   = s * (1.f / 64.f);
        float var = fmaxf(ss * (1.f / 64.f) - m * m, 0.f);
        float inv = rsqrtf(var + 1e-5f);
        xsT[lane * 68 + r]        = (a0 - m) * inv * __ldg(&g2[lane])      + __ldg(&b2[lane]);
        xsT[(lane + 32) * 68 + r] = (a1 - m) * inv * __ldg(&g2[lane + 32]) + __ldg(&b2[lane + 32]);
    }
    __syncthreads();

    {
        int mcol = tid & 255, half = tid >> 8;
#pragma unroll
        for (int g = 0; g < 4; ++g) {
            int r0 = half * 32 + g * 8;
            float bb = b1s[mcol];
            float acc[8];
#pragma unroll
            for (int i = 0; i < 8; ++i) acc[i] = bb;
#pragma unroll 4
            for (int k = 0; k < 64; ++k) {
                float wv  = w1s[k * 256 + mcol];
                float4 xa = *(const float4*)&xsT[k * 68 + r0];
                float4 xb = *(const float4*)&xsT[k * 68 + r0 + 4];
                acc[0] = fmaf(xa.x, wv, acc[0]);
                acc[1] = fmaf(xa.y, wv, acc[1]);
                acc[2] = fmaf(xa.z, wv, acc[2]);
                acc[3] = fmaf(xa.w, wv, acc[3]);
                acc[4] = fmaf(xb.x, wv, acc[4]);
                acc[5] = fmaf(xb.y, wv, acc[5]);
                acc[6] = fmaf(xb.z, wv, acc[6]);
                acc[7] = fmaf(xb.w, wv, acc[7]);
            }
#pragma unroll
            for (int i = 0; i < 8; ++i) {
                float xv = acc[i];
                float u = 0.7978845608028654f * (xv + 0.044715f * xv * xv * xv);
                float th;
                asm("tanh.approx.f32 %0, %1;" : "=f"(th) : "f"(u));
                h1T[mcol * 68 + r0 + i] = 0.5f * xv * (1.f + th);
            }
        }
    }
    __syncthreads();

    {
        int c = tid & 63, rg = tid >> 6;   // 8 row-groups of 8
        float bb = __ldg(&b2o[c]);
        float acc[8];
#pragma unroll
        for (int i = 0; i < 8; ++i) acc[i] = bb;
#pragma unroll 2
        for (int k = 0; k < 256; ++k) {
            float wv  = w2s[k * 64 + c];
            float4 ha = *(const float4*)&h1T[k * 68 + rg * 8];
            float4 hb = *(const float4*)&h1T[k * 68 + rg * 8 + 4];
            acc[0] = fmaf(ha.x, wv, acc[0]);
            acc[1] = fmaf(ha.y, wv, acc[1]);
            acc[2] = fmaf(ha.z, wv, acc[2]);
            acc[3] = fmaf(ha.w, wv, acc[3]);
            acc[4] = fmaf(hb.x, wv, acc[4]);
            acc[5] = fmaf(hb.y, wv, acc[5]);
            acc[6] = fmaf(hb.z, wv, acc[6]);
            acc[7] = fmaf(hb.w, wv, acc[7]);
        }
#pragma unroll
        for (int i = 0; i < 8; ++i) {
            size_t row = (size_t)rowBase + rg * 8 + i;
            out[row * 64 + c] = fmaf(0.5f, acc[i], g_x[row * 64 + c]);
        }
    }
}

// ---------------- launch ----------------
extern "C" void kernel_launch(void* const* d_in, const int* in_sizes, int n_in,
                              void* d_out, int out_size) {
    (void)in_sizes; (void)n_in; (void)out_size;
    const float* inputs = (const float*)d_in[0];
    const float* coords = (const float*)d_in[1];
    const void*  maskp  = d_in[2];
    const float* ln1g   = (const float*)d_in[3];
    const float* ln1b   = (const float*)d_in[4];
    const float* ln2g   = (const float*)d_in[5];
    const float* ln2b   = (const float*)d_in[6];
    const float* wqkv   = (const float*)d_in[7];
    const float* bqkv   = (const float*)d_in[8];
    const float* wproj  = (const float*)d_in[9];
    const float* bproj  = (const float*)d_in[10];
    const float* w1     = (const float*)d_in[11];
    const float* b1     = (const float*)d_in[12];
    const float* w2     = (const float*)d_in[13];
    const float* b2     = (const float*)d_in[14];
    float* out = (float*)d_out;

    cudaFuncSetAttribute(k1_ln_qkv, cudaFuncAttributeMaxDynamicSharedMemorySize, 59136);
    cudaFuncSetAttribute(k4_mlp,    cudaFuncAttributeMaxDynamicSharedMemorySize, 219136);

    k0_mask<<<64, 256>>>(maskp);
    k2a_bins<<<4, 1024>>>(coords);
    k1_ln_qkv<<<512, 256, 59136>>>(inputs, ln1g, ln1b, wqkv, bqkv);
    k2b_knn<<<dim3(512, 4), 256>>>(coords);
    k3_attn<<<256, 256>>>(inputs, wproj, bproj);
    k4_mlp<<<256, 512, 219136>>>(ln2g, ln2b, w1, b1, w2, b2, out);
}

// round 17
// speedup vs baseline: 1.9837x; 1.1174x over previous
#include <cuda_runtime.h>
#include <cuda_bf16.h>
#include <cstdint>

#define Bb 4
#define Nn 4096
#define Cc 64
#define Hh 4
#define DH 16
#define KNNk 10
#define KSk 4
#define Mm 256
#define ROWS_TOT (Bb * Nn)
#define INF_F __int_as_float(0x7f800000)
#define INFKEY 0x7F80000000000000ull

// ---------------- scratch (device globals; no allocation allowed) ----------------
__device__ float g_qkv[ROWS_TOT * 192];   // [row][q(64) k(64) v(64)]
__device__ float g_x[ROWS_TOT * 64];      // residual after attention
__device__ int   g_nbr[ROWS_TOT * KNNk];  // per-batch-local neighbor indices
__device__ unsigned char g_mask[ROWS_TOT];
__device__ float4 g_bpts[Bb * Nn];        // binned unmasked points (x,y,z,idx-bits)
__device__ int2   g_cellrange[Bb * 4096]; // per-cell (start, count) into g_bpts
__device__ int    g_qord[Bb * Nn];        // all queries sorted by cell (locality)

// ---------------- k0: normalize mask dtype (u8 / i32 / f32) into g_mask ----------
__global__ void k0_mask(const void* mp) {
    __shared__ int mode;
    const unsigned char* u = (const unsigned char*)mp;
    if (threadIdx.x == 0) {
        bool anyHigh = false, anyOff = false;
        for (int i = 0; i < 256; ++i) {
            unsigned char b = u[i];
            if (b > 1) anyHigh = true;
            if ((i & 3) != 0 && b != 0) anyOff = true;
        }
        mode = anyHigh ? 2 : (anyOff ? 0 : 1);
    }
    __syncthreads();
    int i = blockIdx.x * blockDim.x + threadIdx.x;
    unsigned char v;
    if (mode == 0)      v = (u[i] != 0);
    else if (mode == 1) v = (((const int*)mp)[i] != 0);
    else                v = (((const float*)mp)[i] != 0.0f);
    g_mask[i] = v;
}

// ---------------- k1: LN1 + QKV GEMM (32 rows / block) ----------------
__global__ void k1_ln_qkv(const float* __restrict__ x,
                          const float* __restrict__ g1, const float* __restrict__ b1,
                          const float* __restrict__ wq, const float* __restrict__ bq) {
    extern __shared__ float sm1[];
    float* ws  = sm1;            // 12288 = 64*192
    float* bs  = ws + 12288;     // 192
    float* xsT = bs + 192;       // 64 * 36 (transposed x-hat, pitch 36)
    int tid = threadIdx.x;
    int rowBase = blockIdx.x * 32;

    for (int i = tid; i < 12288; i += 256) ws[i] = wq[i];
    if (tid < 192) bs[tid] = bq[tid];

    int w = tid >> 5, lane = tid & 31;
#pragma unroll
    for (int rr = 0; rr < 4; ++rr) {
        int r = w * 4 + rr;
        const float* xr = x + (size_t)(rowBase + r) * 64;
        float a0 = xr[lane], a1 = xr[lane + 32];
        float s = a0 + a1, ss = a0 * a0 + a1 * a1;
#pragma unroll
        for (int o = 16; o; o >>= 1) {
            s  += __shfl_xor_sync(0xffffffffu, s, o);
            ss += __shfl_xor_sync(0xffffffffu, ss, o);
        }
        float m   = s * (1.f / 64.f);
        float var = fmaxf(ss * (1.f / 64.f) - m * m, 0.f);
        float inv = rsqrtf(var + 1e-5f);
        xsT[lane * 36 + r]        = (a0 - m) * inv * __ldg(&g1[lane])      + __ldg(&b1[lane]);
        xsT[(lane + 32) * 36 + r] = (a1 - m) * inv * __ldg(&g1[lane + 32]) + __ldg(&b1[lane + 32]);
    }
    __syncthreads();

    if (tid < 192) {
        int c = tid;
#pragma unroll
        for (int g = 0; g < 4; ++g) {
            float bb = bs[c];
            float acc[8];
#pragma unroll
            for (int i = 0; i < 8; ++i) acc[i] = bb;
#pragma unroll 4
            for (int k = 0; k < 64; ++k) {
                float wv  = ws[k * 192 + c];
                float4 xa = *(const float4*)&xsT[k * 36 + g * 8];
                float4 xb = *(const float4*)&xsT[k * 36 + g * 8 + 4];
                acc[0] = fmaf(xa.x, wv, acc[0]);
                acc[1] = fmaf(xa.y, wv, acc[1]);
                acc[2] = fmaf(xa.z, wv, acc[2]);
                acc[3] = fmaf(xa.w, wv, acc[3]);
                acc[4] = fmaf(xb.x, wv, acc[4]);
                acc[5] = fmaf(xb.y, wv, acc[5]);
                acc[6] = fmaf(xb.z, wv, acc[6]);
                acc[7] = fmaf(xb.w, wv, acc[7]);
            }
#pragma unroll
            for (int i = 0; i < 8; ++i)
                g_qkv[(size_t)(rowBase + g * 8 + i) * 192 + c] = acc[i];
        }
    }
}

// ---------------- k2a: bin points into 16^3 grid (counting sort) -----------------
// blockIdx.y selects the pass (independent outputs -> run concurrently):
//   pass 0: unmasked points -> g_bpts + g_cellrange.   pass 1: all -> g_qord.
__global__ void k2a_bins(const float* __restrict__ coords) {
    __shared__ unsigned int cnts[4096];
    __shared__ unsigned int starts[4096];
    __shared__ unsigned int wsum[32];
    int b = blockIdx.x, pass = blockIdx.y, tid = threadIdx.x;   // 1024 threads
    const float* cb = coords + (size_t)b * Nn * 3;
    int lane = tid & 31, wid = tid >> 5;

    for (int i = tid; i < 4096; i += 1024) cnts[i] = 0;
    __syncthreads();
    for (int i = tid; i < Nn; i += 1024) {
        if (pass == 0 && !g_mask[b * Nn + i]) continue;
        float x = cb[i * 3], y = cb[i * 3 + 1], z = cb[i * 3 + 2];
        int cx = min(15, (int)x), cy = min(15, (int)y), cz = min(15, (int)z);
        atomicAdd(&cnts[(cz * 16 + cy) * 16 + cx], 1u);
    }
    __syncthreads();
    unsigned v0 = cnts[tid * 4], v1 = cnts[tid * 4 + 1],
             v2 = cnts[tid * 4 + 2], v3 = cnts[tid * 4 + 3];
    unsigned tot = v0 + v1 + v2 + v3;
    unsigned inc = tot;
#pragma unroll
    for (int o = 1; o < 32; o <<= 1) {
        unsigned n = __shfl_up_sync(0xffffffffu, inc, o);
        if (lane >= o) inc += n;
    }
    if (lane == 31) wsum[wid] = inc;
    __syncthreads();
    if (wid == 0) {
        unsigned t = wsum[lane];
        unsigned i2 = t;
#pragma unroll
        for (int o = 1; o < 32; o <<= 1) {
            unsigned n = __shfl_up_sync(0xffffffffu, i2, o);
            if (lane >= o) i2 += n;
        }
        wsum[lane] = i2 - t;
    }
    __syncthreads();
    unsigned base = wsum[wid] + (inc - tot);
    unsigned s0 = base, s1 = base + v0, s2 = s1 + v1, s3 = s2 + v2;
    starts[tid * 4] = s0; starts[tid * 4 + 1] = s1;
    starts[tid * 4 + 2] = s2; starts[tid * 4 + 3] = s3;
    if (pass == 0) {
        g_cellrange[b * 4096 + tid * 4 + 0] = make_int2((int)s0, (int)v0);
        g_cellrange[b * 4096 + tid * 4 + 1] = make_int2((int)s1, (int)v1);
        g_cellrange[b * 4096 + tid * 4 + 2] = make_int2((int)s2, (int)v2);
        g_cellrange[b * 4096 + tid * 4 + 3] = make_int2((int)s3, (int)v3);
    }
    __syncthreads();
    for (int i = tid; i < Nn; i += 1024) {
        if (pass == 0 && !g_mask[b * Nn + i]) continue;
        float x = cb[i * 3], y = cb[i * 3 + 1], z = cb[i * 3 + 2];
        int cx = min(15, (int)x), cy = min(15, (int)y), cz = min(15, (int)z);
        unsigned pos = atomicAdd(&starts[(cz * 16 + cy) * 16 + cx], 1u);
        if (pass == 0) g_bpts[b * Nn + pos] = make_float4(x, y, z, __int_as_float(i));
        else           g_qord[b * Nn + pos] = i;
    }
}

// ---------------- k2b: exact KNN, warp-per-query, shifted-window flat scan -------
// Window: 5x5x5 cells with origin w?0 = clamp(qc?-2, 0, 11) — always fully in
// volume AND a superset of the centered-clamped Chebyshev-2 neighborhood, so the
// shell bound ((s-1)^2 > d9 -> ring s irrelevant) remains exact. Expected ~62
// candidates everywhere (boundary included) -> shell path fires ~4% of queries.
// Shell cells inside the window are skipped (no duplicate insertion).
__global__ void k2b_knn(const float* __restrict__ coords) {
    int lane = threadIdx.x & 31, warp = threadIdx.x >> 5;
    int b = blockIdx.y;
    int t = blockIdx.x * 8 + warp;                   // bin-ordered query slot
    int q = g_qord[b * Nn + t];
    const float* cb = coords + (size_t)b * Nn * 3;
    float qx = cb[q * 3], qy = cb[q * 3 + 1], qz = cb[q * 3 + 2];
    float qq = fmaf(qx, qx, fmaf(qy, qy, qz * qz));
    float nx = -2.f * qx, ny = -2.f * qy, nz = -2.f * qz;
    int qcx = min(15, (int)qx), qcy = min(15, (int)qy), qcz = min(15, (int)qz);
    int wx0 = min(max(qcx - 2, 0), 11);
    int wy0 = min(max(qcy - 2, 0), 11);
    int wz0 = min(max(qcz - 2, 0), 11);

    const float4* bp = &g_bpts[b * Nn];
    const int2*   cr = &g_cellrange[b * 4096];

    // ---- row spans (lane < 25 owns one (dz,dy) row of the window) ----
    int rowLen = 0, rowStart = 0;
    if (lane < 25) {
        int z = wz0 + lane / 5, y = wy0 + lane % 5;
        int cbase = (z * 16 + y) * 16;
        int2 rlo = __ldg(&cr[cbase + wx0]);
        int2 rhi = __ldg(&cr[cbase + wx0 + 4]);
        rowStart = rlo.x;
        rowLen   = rhi.x + rhi.y - rlo.x;
    }
    int pfx = rowLen;
#pragma unroll
    for (int o = 1; o < 32; o <<= 1) {
        int n = __shfl_up_sync(0xffffffffu, pfx, o);
        if (lane >= o) pfx += n;
    }
    int total = __shfl_sync(0xffffffffu, pfx, 31);
    int exq = (lane < 25) ? (pfx - rowLen) : 0x7fffffff;  // exclusive prefix

    float gd = INF_F; int gi = 0;                    // lane r holds rank-r result
    float d9;

    // u64 machinery (overflow fallback + outer shells)
    unsigned long long key[KNNk];
    unsigned long long gkey = INFKEY;
    auto insertKey = [&](unsigned long long kk) {
#pragma unroll
        for (int k = 0; k < KNNk; ++k) {
            bool pr = kk < key[k];
            unsigned long long tv = key[k];
            key[k] = pr ? kk : tv;
            kk     = pr ? tv : kk;
        }
    };
    auto merge10 = [&]() {
#pragma unroll
        for (int r = 0; r < KNNk; ++r) {
            unsigned long long m = key[0];
#pragma unroll
            for (int o = 16; o; o >>= 1) {
                unsigned long long om = __shfl_xor_sync(0xffffffffu, m, o);
                m = (om < m) ? om : m;
            }
            if (lane == r) gkey = m;
            if (key[0] == m) {
#pragma unroll
                for (int k = 0; k < KNNk - 1; ++k) key[k] = key[k + 1];
                key[KNNk - 1] = INFKEY;
            }
        }
    };

    if (total <= 128) {
        // ---- fast path: flattened, load-balanced, warp-uniform ----
        float sd[4]; int si[4];
#pragma unroll
        for (int i = 0; i < 4; ++i) { sd[i] = INF_F; si[i] = 0; }
        if (total > 0) {
#pragma unroll 4
            for (int it = 0; it * 32 < total && it < 4; ++it) {   // warp-uniform trip
                int c = it * 32 + lane;
                int cq = min(c, total - 1);                       // clamp: stay convergent
                int r = 0, v;
                v = __shfl_sync(0xffffffffu, exq, 16);     if (v <= cq) r = 16;
                v = __shfl_sync(0xffffffffu, exq, r + 8);  if (v <= cq) r += 8;
                v = __shfl_sync(0xffffffffu, exq, r + 4);  if (v <= cq) r += 4;
                v = __shfl_sync(0xffffffffu, exq, r + 2);  if (v <= cq) r += 2;
                v = __shfl_sync(0xffffffffu, exq, r + 1);  if (v <= cq) r += 1;
                int ex = __shfl_sync(0xffffffffu, exq, r);
                int st = __shfl_sync(0xffffffffu, rowStart, r);
                float4 c4 = __ldg(&bp[st + (cq - ex)]);
                float cc = fmaf(c4.x, c4.x, fmaf(c4.y, c4.y, c4.z * c4.z));
                float dd = fmaf(nx, c4.x, fmaf(ny, c4.y, fmaf(nz, c4.z, cc)));
                float dt = fmaxf(dd + qq, 0.f);
                sd[it] = (c < total) ? dt : INF_F;
                si[it] = (c < total) ? __float_as_int(c4.w) : 0;
            }
        }
        // sort 4 per lane (network 0-1,2-3,0-2,1-3,1-2), static indices only
#define CSW(A,B) { bool sw = sd[A] > sd[B]; float td = sd[A]; int ti = si[A]; \
                   sd[A] = sw ? sd[B] : sd[A]; si[A] = sw ? si[B] : si[A];     \
                   sd[B] = sw ? td : sd[B];    si[B] = sw ? ti : si[B]; }
        CSW(0,1) CSW(2,3) CSW(0,2) CSW(1,3) CSW(1,2)
#undef CSW
        // 10 extraction rounds on per-lane heads (float min + ballot winner)
#pragma unroll
        for (int r = 0; r < KNNk; ++r) {
            float m = sd[0];
#pragma unroll
            for (int o = 16; o; o >>= 1)
                m = fminf(m, __shfl_xor_sync(0xffffffffu, m, o));
            unsigned ball = __ballot_sync(0xffffffffu, sd[0] == m);
            int src = __ffs(ball) - 1;
            int wi = __shfl_sync(0xffffffffu, si[0], src);
            if (lane == r) { gd = m; gi = wi; }
            if (lane == src) {
                sd[0] = sd[1]; si[0] = si[1];
                sd[1] = sd[2]; si[1] = si[2];
                sd[2] = sd[3]; si[2] = si[3];
                sd[3] = INF_F; si[3] = 0;
            }
        }
        d9 = __shfl_sync(0xffffffffu, gd, 9);
    } else {
        // ---- overflow fallback (astronomically rare): u64, window cells ----
#pragma unroll
        for (int i = 0; i < KNNk; ++i) key[i] = INFKEY;
#pragma unroll
        for (int it = 0; it < 4; ++it) {
            int c5 = lane + it * 32;
            if (c5 < 125) {
                int dz = c5 / 25;
                int rem = c5 - dz * 25;
                int z = wz0 + dz, y = wy0 + rem / 5, xx = wx0 + rem % 5;
                int2 rg = __ldg(&cr[(z * 16 + y) * 16 + xx]);
                int pe = rg.x + rg.y;
                for (int p = rg.x; p < pe; ++p) {
                    float4 c = __ldg(&bp[p]);
                    float cc = fmaf(c.x, c.x, fmaf(c.y, c.y, c.z * c.z));
                    float dd = fmaf(nx, c.x, fmaf(ny, c.y, fmaf(nz, c.z, cc)));
                    float dt = fmaxf(dd + qq, 0.f);
                    unsigned long long kk =
                        ((unsigned long long)__float_as_uint(dt) << 32) |
                        (unsigned int)__float_as_int(c.w);
                    if (kk < key[KNNk - 1]) insertKey(kk);
                }
            }
        }
        gkey = INFKEY;
        merge10();
        gd = __uint_as_float((unsigned)(gkey >> 32));
        gi = (int)(unsigned)(gkey & 0xffffffffu);
        d9 = __shfl_sync(0xffffffffu, gd, 9);
    }

    // ---- outer shells s>=3 (rare now; u64 path seeded with current top-10) ----
    if (d9 >= 4.0f) {
#pragma unroll
        for (int i = 0; i < KNNk; ++i) key[i] = INFKEY;
        gkey = ((unsigned long long)__float_as_uint(gd) << 32) | (unsigned int)gi;
        for (int s = 3; s < 16; ++s) {
            if ((float)((s - 1) * (s - 1)) > d9) break;      // warp-uniform
            int w1 = 2 * s + 1, ncell = w1 * w1 * w1;
            bool added = false;
            for (int c5 = lane; c5 < ncell; c5 += 32) {
                int dz = c5 / (w1 * w1) - s, dy = (c5 / w1) % w1 - s, dx = c5 % w1 - s;
                int m = max(abs(dx), max(abs(dy), abs(dz)));
                if (m != s) continue;                        // ring only
                int z = qcz + dz, y = qcy + dy, xx = qcx + dx;
                if ((unsigned)xx > 15u || (unsigned)y > 15u || (unsigned)z > 15u) continue;
                if (xx >= wx0 && xx <= wx0 + 4 &&
                    y  >= wy0 && y  <= wy0 + 4 &&
                    z  >= wz0 && z  <= wz0 + 4) continue;    // already scanned
                int2 rg = __ldg(&cr[(z * 16 + y) * 16 + xx]);
                int pe = rg.x + rg.y;
                for (int p = rg.x; p < pe; ++p) {
                    float4 c = __ldg(&bp[p]);
                    float cc = fmaf(c.x, c.x, fmaf(c.y, c.y, c.z * c.z));
                    float dd = fmaf(nx, c.x, fmaf(ny, c.y, fmaf(nz, c.z, cc)));
                    float dt = fmaxf(dd + qq, 0.f);
                    unsigned long long kk =
                        ((unsigned long long)__float_as_uint(dt) << 32) |
                        (unsigned int)__float_as_int(c.w);
                    if (kk < key[KNNk - 1]) { insertKey(kk); added = true; }
                }
            }
            if (__any_sync(0xffffffffu, added)) {
                insertKey(gkey);     // put extracted entries back in play
                gkey = INFKEY;
                merge10();
                d9 = __uint_as_float((unsigned)(__shfl_sync(0xffffffffu, gkey, 9) >> 32));
            }
        }
        gi = (int)(unsigned)(gkey & 0xffffffffu);
    }

    if (lane < KNNk)
        g_nbr[(size_t)(b * Nn + q) * KNNk + lane] = gi;
}

// ---------------- k3: attention (64 rows / block, warp loops 8 rows) -------------
__global__ void k3_attn(const float* __restrict__ inputs,
                        const float* __restrict__ wproj, const float* __restrict__ bproj) {
    __shared__ float wp[4096];
    __shared__ float bp[64];
    __shared__ __align__(16) float qs[8][64];
    __shared__ float sc[8][40];
    __shared__ float swt[8][16];
    __shared__ int   sjg[8][16];
    __shared__ int   snb[8][KNNk];
    __shared__ float ovec[8][64];

    int tid = threadIdx.x, w = tid >> 5, lane = tid & 31;
    for (int i = tid; i < 4096; i += 256) wp[i] = wproj[i];
    if (tid < 64) bp[tid] = bproj[tid];
    __syncthreads();

    for (int r8 = 0; r8 < 8; ++r8) {
        int row  = blockIdx.x * 64 + w * 8 + r8;
        int base = row & ~(Nn - 1);

        const float* qr = &g_qkv[(size_t)row * 192];
        qs[w][lane]      = qr[lane];
        qs[w][lane + 32] = qr[lane + 32];
        if (lane < KNNk) snb[w][lane] = g_nbr[(size_t)row * KNNk + lane];
        __syncwarp();

        for (int t = lane; t < Hh * KNNk; t += 32) {
            int h = t / KNNk, j = t - h * KNNk;
            int jl = snb[w][j];
            const float* kp = &g_qkv[(size_t)(base + jl) * 192 + 64 + h * DH];
            const float* qp = &qs[w][h * DH];
            float4 k0 = *(const float4*)(kp);
            float4 k1 = *(const float4*)(kp + 4);
            float4 k2 = *(const float4*)(kp + 8);
            float4 k3 = *(const float4*)(kp + 12);
            float4 q0 = *(const float4*)(qp);
            float4 q1 = *(const float4*)(qp + 4);
            float4 q2 = *(const float4*)(qp + 8);
            float4 q3 = *(const float4*)(qp + 12);
            float acc = k0.x * q0.x + k0.y * q0.y + k0.z * q0.z + k0.w * q0.w
                      + k1.x * q1.x + k1.y * q1.y + k1.z * q1.z + k1.w * q1.w
                      + k2.x * q2.x + k2.y * q2.y + k2.z * q2.z + k2.w * q2.w
                      + k3.x * q3.x + k3.y * q3.y + k3.z * q3.z + k3.w * q3.w;
            float s = acc * 0.25f;
            if (!g_mask[base + jl]) s -= 1e9f;
            sc[w][t] = s;
        }
        __syncwarp();

        if (lane < Hh) {
            int h = lane;
            float bv0 = -3.4e38f, bv1 = -3.4e38f, bv2 = -3.4e38f, bv3 = -3.4e38f;
            int   bi0 = 0, bi1 = 0, bi2 = 0, bi3 = 0;
#pragma unroll
            for (int j = 0; j < KNNk; ++j) {
                float v = sc[w][h * KNNk + j]; int vi = j;
                if (v > bv0) { float t0 = bv0; int ti = bi0; bv0 = v; bi0 = vi; v = t0; vi = ti; }
                if (v > bv1) { float t0 = bv1; int ti = bi1; bv1 = v; bi1 = vi; v = t0; vi = ti; }
                if (v > bv2) { float t0 = bv2; int ti = bi2; bv2 = v; bi2 = vi; v = t0; vi = ti; }
                if (v > bv3) { float t0 = bv3; int ti = bi3; bv3 = v; bi3 = vi; v = t0; vi = ti; }
            }
            float e1 = __expf(bv1 - bv0), e2 = __expf(bv2 - bv0), e3 = __expf(bv3 - bv0);
            float inv = 1.f / (1.f + e1 + e2 + e3);
            swt[w][h * 4 + 0] = inv;
            swt[w][h * 4 + 1] = e1 * inv;
            swt[w][h * 4 + 2] = e2 * inv;
            swt[w][h * 4 + 3] = e3 * inv;
            sjg[w][h * 4 + 0] = base + snb[w][bi0];
            sjg[w][h * 4 + 1] = base + snb[w][bi1];
            sjg[w][h * 4 + 2] = base + snb[w][bi2];
            sjg[w][h * 4 + 3] = base + snb[w][bi3];
        }
        __syncwarp();

        {
            int c0 = lane, c1 = lane + 32;
            int h0 = c0 >> 4, h1 = c1 >> 4;
            float a0 = 0.f, a1 = 0.f;
#pragma unroll
            for (int s = 0; s < KSk; ++s) {
                a0 += swt[w][h0 * 4 + s] * g_qkv[(size_t)sjg[w][h0 * 4 + s] * 192 + 128 + c0];
                a1 += swt[w][h1 * 4 + s] * g_qkv[(size_t)sjg[w][h1 * 4 + s] * 192 + 128 + c1];
            }
            ovec[w][c0] = a0; ovec[w][c1] = a1;
        }
        __syncwarp();

        {
            float acc0 = bp[lane], acc1 = bp[lane + 32];
#pragma unroll 4
            for (int k = 0; k < 64; ++k) {
                float ov = ovec[w][k];
                acc0 = fmaf(ov, wp[k * 64 + lane], acc0);
                acc1 = fmaf(ov, wp[k * 64 + lane + 32], acc1);
            }
            float half0 = g_mask[row] ? 0.5f : 0.f;
            const float* ir = inputs + (size_t)row * 64;
            g_x[(size_t)row * 64 + lane]      = fmaf(half0, acc0, ir[lane]);
            g_x[(size_t)row * 64 + lane + 32] = fmaf(half0, acc1, ir[lane + 32]);
        }
        __syncwarp();
    }
}

// ---------------- k4: LN2 + MLP (64 rows / block, 512 threads) -------------------
__global__ void k4_mlp(const float* __restrict__ g2, const float* __restrict__ b2,
                       const float* __restrict__ w1, const float* __restrict__ b1,
                       const float* __restrict__ w2, const float* __restrict__ b2o,
                       float* __restrict__ out) {
    extern __shared__ float sm4[];
    float* w1s = sm4;             // 16384 = 64*256
    float* w2s = w1s + 16384;     // 16384 = 256*64
    float* b1s = w2s + 16384;     // 256
    float* xsT = b1s + 256;       // 64 * 68
    float* h1T = xsT + 4352;      // 256 * 68
    int tid = threadIdx.x;        // 512 threads
    int rowBase = blockIdx.x * 64;

    for (int i = tid; i < 16384; i += 512) { w1s[i] = w1[i]; w2s[i] = w2[i]; }
    if (tid < 256) b1s[tid] = b1[tid];

    int w = tid >> 5, lane = tid & 31;   // 16 warps x 4 rows = 64 rows
#pragma unroll
    for (int rr = 0; rr < 4; ++rr) {
        int r = w * 4 + rr;
        const float* xr = &g_x[(size_t)(rowBase + r) * 64];
        float a0 = xr[lane], a1 = xr[lane + 32];
        float s = a0 + a1, ss = a0 * a0 + a1 * a1;
#pragma unroll
        for (int o = 16; o; o >>= 1) {
            s  += __shfl_xor_sync(0xffffffffu, s, o);
            ss += __shfl_xor_sync(0xffffffffu, ss, o);
        }
        float m   = s * (1.f / 64.f);
        float var = fmaxf(ss * (1.f / 64.f) - m * m, 0.f);
        float inv = rsqrtf(var + 1e-5f);
        xsT[lane * 68 + r]        = (a0 - m) * inv * __ldg(&g2[lane])      + __ldg(&b2[lane]);
        xsT[(lane + 32) * 68 + r] = (a1 - m) * inv * __ldg(&g2[lane + 32]) + __ldg(&b2[lane + 32]);
    }
    __syncthreads();

    {
        int mcol = tid & 255, half = tid >> 8;
#pragma unroll
        for (int g = 0; g < 4; ++g) {
            int r0 = half * 32 + g * 8;
            float bb = b1s[mcol];
            float acc[8];
#pragma unroll
            for (int i = 0; i < 8; ++i) acc[i] = bb;
#pragma unroll 4
            for (int k = 0; k < 64; ++k) {
                float wv  = w1s[k * 256 + mcol];
                float4 xa = *(const float4*)&xsT[k * 68 + r0];
                float4 xb = *(const float4*)&xsT[k * 68 + r0 + 4];
                acc[0] = fmaf(xa.x, wv, acc[0]);
                acc[1] = fmaf(xa.y, wv, acc[1]);
                acc[2] = fmaf(xa.z, wv, acc[2]);
                acc[3] = fmaf(xa.w, wv, acc[3]);
                acc[4] = fmaf(xb.x, wv, acc[4]);
                acc[5] = fmaf(xb.y, wv, acc[5]);
                acc[6] = fmaf(xb.z, wv, acc[6]);
                acc[7] = fmaf(xb.w, wv, acc[7]);
            }
#pragma unroll
            for (int i = 0; i < 8; ++i) {
                float xv = acc[i];
                float u = 0.7978845608028654f * (xv + 0.044715f * xv * xv * xv);
                float th;
                asm("tanh.approx.f32 %0, %1;" : "=f"(th) : "f"(u));
                h1T[mcol * 68 + r0 + i] = 0.5f * xv * (1.f + th);
            }
        }
    }
    __syncthreads();

    {
        int c = tid & 63, rg = tid >> 6;   // 8 row-groups of 8
        float bb = __ldg(&b2o[c]);
        float acc[8];
#pragma unroll
        for (int i = 0; i < 8; ++i) acc[i] = bb;
#pragma unroll 2
        for (int k = 0; k < 256; ++k) {
            float wv  = w2s[k * 64 + c];
            float4 ha = *(const float4*)&h1T[k * 68 + rg * 8];
            float4 hb = *(const float4*)&h1T[k * 68 + rg * 8 + 4];
            acc[0] = fmaf(ha.x, wv, acc[0]);
            acc[1] = fmaf(ha.y, wv, acc[1]);
            acc[2] = fmaf(ha.z, wv, acc[2]);
            acc[3] = fmaf(ha.w, wv, acc[3]);
            acc[4] = fmaf(hb.x, wv, acc[4]);
            acc[5] = fmaf(hb.y, wv, acc[5]);
            acc[6] = fmaf(hb.z, wv, acc[6]);
            acc[7] = fmaf(hb.w, wv, acc[7]);
        }
#pragma unroll
        for (int i = 0; i < 8; ++i) {
            size_t row = (size_t)rowBase + rg * 8 + i;
            out[row * 64 + c] = fmaf(0.5f, acc[i], g_x[row * 64 + c]);
        }
    }
}

// ---------------- launch ----------------
extern "C" void kernel_launch(void* const* d_in, const int* in_sizes, int n_in,
                              void* d_out, int out_size) {
    (void)in_sizes; (void)n_in; (void)out_size;
    const float* inputs = (const float*)d_in[0];
    const float* coords = (const float*)d_in[1];
    const void*  maskp  = d_in[2];
    const float* ln1g   = (const float*)d_in[3];
    const float* ln1b   = (const float*)d_in[4];
    const float* ln2g   = (const float*)d_in[5];
    const float* ln2b   = (const float*)d_in[6];
    const float* wqkv   = (const float*)d_in[7];
    const float* bqkv   = (const float*)d_in[8];
    const float* wproj  = (const float*)d_in[9];
    const float* bproj  = (const float*)d_in[10];
    const float* w1     = (const float*)d_in[11];
    const float* b1     = (const float*)d_in[12];
    const float* w2     = (const float*)d_in[13];
    const float* b2     = (const float*)d_in[14];
    float* out = (float*)d_out;

    cudaFuncSetAttribute(k1_ln_qkv, cudaFuncAttributeMaxDynamicSharedMemorySize, 59136);
    cudaFuncSetAttribute(k4_mlp,    cudaFuncAttributeMaxDynamicSharedMemorySize, 219136);

    k0_mask<<<64, 256>>>(maskp);
    k2a_bins<<<dim3(4, 2), 1024>>>(coords);
    k1_ln_qkv<<<512, 256, 59136>>>(inputs, ln1g, ln1b, wqkv, bqkv);
    k2b_knn<<<dim3(512, 4), 256>>>(coords);
    k3_attn<<<256, 256>>>(inputs, wproj, bproj);
    k4_mlp<<<256, 512, 219136>>>(ln2g, ln2b, w1, b1, w2, b2, out);
}